// round 4
// baseline (speedup 1.0000x reference)
#include <cuda_runtime.h>
#include <cuda_bf16.h>
#include <cstdint>

#define F 128
#define MAXN 50000
#define NPAD 50176
#define MAXE 800000
#define NBLK 8
#define SCAN_NB ((MAXN + 1023) / 1024)   // 49

// ---------------- device scratch (static globals; no runtime alloc) ----------------
__device__ float g_bufA[MAXN * F];
__device__ float g_bufB[MAXN * F];
__device__ __nv_bfloat16 g_termsh[(size_t)NBLK * NPAD * F];
__device__ __nv_bfloat16 g_termsm[(size_t)NBLK * NPAD * F];
__device__ int   g_rowstart[MAXN + 1];
__device__ int   g_cnt[MAXN];
__device__ int   g_bsum[64];
__device__ int   g_boff[66];
__device__ int   g_csrs[MAXE];
__device__ float g_csrw[MAXE];
__device__ __nv_bfloat16 g_wth[F * NBLK * F];  // W^T hi  [128 n][1024 k]
__device__ __nv_bfloat16 g_wtm[F * NBLK * F];  // W^T mid

// ---------------- helpers ----------------
__device__ __forceinline__ uint32_t smem_u32(const void* p) {
    uint32_t a;
    asm("{ .reg .u64 t; cvta.to.shared.u64 t, %1; cvt.u32.u64 %0, t; }" : "=r"(a) : "l"(p));
    return a;
}
__device__ __forceinline__ void ldsm4(uint32_t* r, uint32_t addr) {
    asm volatile("ldmatrix.sync.aligned.m8n8.x4.shared.b16 {%0,%1,%2,%3}, [%4];"
        : "=r"(r[0]), "=r"(r[1]), "=r"(r[2]), "=r"(r[3]) : "r"(addr));
}
__device__ __forceinline__ void mma16816(float* c, const uint32_t* a, const uint32_t* b) {
    asm volatile("mma.sync.aligned.m16n8k16.row.col.f32.bf16.bf16.f32 "
        "{%0,%1,%2,%3}, {%4,%5,%6,%7}, {%8,%9}, {%0,%1,%2,%3};"
        : "+f"(c[0]), "+f"(c[1]), "+f"(c[2]), "+f"(c[3])
        : "r"(a[0]), "r"(a[1]), "r"(a[2]), "r"(a[3]), "r"(b[0]), "r"(b[1]));
}
__device__ __forceinline__ void split_bf16(float x, __nv_bfloat16& h, __nv_bfloat16& m) {
    h = __float2bfloat16_rn(x);
    m = __float2bfloat16_rn(x - __bfloat162float(h));
}

// ---------------- CSR build ----------------
__global__ void zero_counts_kernel(int n) {
    int i = blockIdx.x * blockDim.x + threadIdx.x;
    if (i < n) g_cnt[i] = 0;
}
__global__ void hist_kernel(const int* __restrict__ edst, int e) {
    int i = blockIdx.x * blockDim.x + threadIdx.x;
    if (i < e) atomicAdd(&g_cnt[edst[i]], 1);
}
// hierarchical scan: A = per-block scan, B = scan of block sums, C = add offsets
__global__ void scanA_kernel(int n) {
    __shared__ int wsum[32];
    int tid = threadIdx.x;
    int i = blockIdx.x * 1024 + tid;
    int v = (i < n) ? g_cnt[i] : 0;
    int lane = tid & 31, w = tid >> 5;
    int x = v;
    #pragma unroll
    for (int off = 1; off < 32; off <<= 1) {
        int t = __shfl_up_sync(0xffffffffu, x, off);
        if (lane >= off) x += t;
    }
    if (lane == 31) wsum[w] = x;
    __syncthreads();
    if (w == 0) {
        int s = wsum[lane];
        #pragma unroll
        for (int off = 1; off < 32; off <<= 1) {
            int t = __shfl_up_sync(0xffffffffu, s, off);
            if (lane >= off) s += t;
        }
        wsum[lane] = s;
    }
    __syncthreads();
    int base = (w > 0) ? wsum[w - 1] : 0;
    if (i < n) g_rowstart[i] = base + x - v;   // block-local exclusive
    if (tid == 0) g_bsum[blockIdx.x] = wsum[31];
}
__global__ void scanB_kernel(int nb) {
    __shared__ int t0;
    int tid = threadIdx.x;  // 64 threads
    int v = (tid < nb) ? g_bsum[tid] : 0;
    int lane = tid & 31, w = tid >> 5;
    int x = v;
    #pragma unroll
    for (int off = 1; off < 32; off <<= 1) {
        int t = __shfl_up_sync(0xffffffffu, x, off);
        if (lane >= off) x += t;
    }
    if (w == 0 && lane == 31) t0 = x;
    __syncthreads();
    int incl = x + (w ? t0 : 0);
    g_boff[tid] = incl - v;
    if (tid == 63) g_boff[64] = incl;  // grand total
}
__global__ void scanC_kernel(int n) {
    int i = blockIdx.x * 1024 + threadIdx.x;
    if (i < n) {
        g_rowstart[i] += g_boff[blockIdx.x];
        g_cnt[i] = 0;  // reset cursor for scatter
    }
    if (i == 0) g_rowstart[n] = g_boff[64];
}
__global__ void scatter_kernel(const int* __restrict__ esrc, const int* __restrict__ edst,
                               const float* __restrict__ ew, int e) {
    int i = blockIdx.x * blockDim.x + threadIdx.x;
    if (i < e) {
        int d = edst[i];
        int p = g_rowstart[d] + atomicAdd(&g_cnt[d], 1);
        g_csrs[p] = esrc[i];
        g_csrw[p] = ew[i];
    }
}

// ---------------- W^T split + term0 convert ----------------
__global__ void wprep_kernel(const float* __restrict__ W) {  // W [1024,128]
    int i = blockIdx.x * blockDim.x + threadIdx.x;
    if (i < 1024 * 128) {
        int k = i >> 7, nn = i & 127;
        __nv_bfloat16 h, m;
        split_bf16(W[i], h, m);
        g_wth[nn * 1024 + k] = h;
        g_wtm[nn * 1024 + k] = m;
    }
}
__global__ void conv0_kernel(const float* __restrict__ src,
                             __nv_bfloat16* __restrict__ th,
                             __nv_bfloat16* __restrict__ tm, int n4) {
    int i = blockIdx.x * blockDim.x + threadIdx.x;
    if (i >= n4) return;
    float4 x = ((const float4*)src)[i];
    __nv_bfloat16 h[4], m[4];
    split_bf16(x.x, h[0], m[0]); split_bf16(x.y, h[1], m[1]);
    split_bf16(x.z, h[2], m[2]); split_bf16(x.w, h[3], m[3]);
    int node = i >> 5, q = i & 31;
    size_t off = (size_t)node * 128 + q * 4;
    *(uint2*)&th[off] = *(uint2*)h;
    *(uint2*)&tm[off] = *(uint2*)m;
}

// ---------------- SpMM (unroll-4, emits bf16 h/m) ----------------
__global__ void spmm_kernel(const float* __restrict__ X, float* __restrict__ Y,
                            __nv_bfloat16* __restrict__ th,
                            __nv_bfloat16* __restrict__ tm, int n) {
    int node = blockIdx.x * blockDim.y + threadIdx.y;
    if (node >= n) return;
    int lane = threadIdx.x;
    int p = g_rowstart[node], end = g_rowstart[node + 1];
    float4 acc = make_float4(0.f, 0.f, 0.f, 0.f);
    const float4* Xv = (const float4*)X;
    for (; p + 4 <= end; p += 4) {
        int s0 = __ldg(&g_csrs[p]),     s1 = __ldg(&g_csrs[p + 1]);
        int s2 = __ldg(&g_csrs[p + 2]), s3 = __ldg(&g_csrs[p + 3]);
        float w0 = __ldg(&g_csrw[p]),     w1 = __ldg(&g_csrw[p + 1]);
        float w2 = __ldg(&g_csrw[p + 2]), w3 = __ldg(&g_csrw[p + 3]);
        float4 x0 = __ldg(&Xv[s0 * 32 + lane]);
        float4 x1 = __ldg(&Xv[s1 * 32 + lane]);
        float4 x2 = __ldg(&Xv[s2 * 32 + lane]);
        float4 x3 = __ldg(&Xv[s3 * 32 + lane]);
        acc.x += w0 * x0.x + w1 * x1.x + w2 * x2.x + w3 * x3.x;
        acc.y += w0 * x0.y + w1 * x1.y + w2 * x2.y + w3 * x3.y;
        acc.z += w0 * x0.z + w1 * x1.z + w2 * x2.z + w3 * x3.z;
        acc.w += w0 * x0.w + w1 * x1.w + w2 * x2.w + w3 * x3.w;
    }
    for (; p < end; ++p) {
        int s = __ldg(&g_csrs[p]);
        float w = __ldg(&g_csrw[p]);
        float4 x = __ldg(&Xv[s * 32 + lane]);
        acc.x += w * x.x; acc.y += w * x.y; acc.z += w * x.z; acc.w += w * x.w;
    }
    ((float4*)Y)[node * 32 + lane] = acc;
    __nv_bfloat16 h[4], m[4];
    split_bf16(acc.x, h[0], m[0]); split_bf16(acc.y, h[1], m[1]);
    split_bf16(acc.z, h[2], m[2]); split_bf16(acc.w, h[3], m[3]);
    size_t off = (size_t)node * 128 + lane * 4;
    *(uint2*)&th[off] = *(uint2*)h;
    *(uint2*)&tm[off] = *(uint2*)m;
}

// ---------------- per-term accumulating GEMM: out (+)= term @ W_t (+bias) -------
// mma.sync bf16x3, CTA tile 128x128, 8 warps of 32x64, K=128 in 2 chunks of 64.
#define A_STRB 144
#define TILE_BYTES (128 * A_STRB)
#define SM_GEMM (4 * TILE_BYTES)

__global__ void __launch_bounds__(256, 2) krylov_gemm_term(
    const __nv_bfloat16* __restrict__ th_t, const __nv_bfloat16* __restrict__ tm_t,
    const __nv_bfloat16* __restrict__ wth, const __nv_bfloat16* __restrict__ wtm,
    int kc0, const float* __restrict__ bias, float* __restrict__ out, int n, int first)
{
    extern __shared__ char smem[];
    char* sAh = smem;
    char* sAm = smem + TILE_BYTES;
    char* sBh = smem + 2 * TILE_BYTES;
    char* sBm = smem + 3 * TILE_BYTES;
    const uint32_t uAh = smem_u32(sAh), uAm = smem_u32(sAm);
    const uint32_t uBh = smem_u32(sBh), uBm = smem_u32(sBm);

    const int tid = threadIdx.x, lane = tid & 31, wid = tid >> 5;
    const int warp_m = (wid & 3) * 32;
    const int warp_n = (wid >> 2) * 64;
    const int r0 = blockIdx.x * 128;

    const int a_rin = (lane & 7) + ((lane >> 3) & 1) * 8;
    const int a_k8  = (lane >> 4);
    const int b_nrow = (lane & 7) + (lane >> 4) * 8;
    const int b_k8   = (lane >> 3) & 1;
    const uint32_t aoff0 = (uint32_t)((warp_m + a_rin) * A_STRB + a_k8 * 16);
    const uint32_t aoff1 = aoff0 + 16 * A_STRB;
    const uint32_t boffb = (uint32_t)((warp_n + b_nrow) * A_STRB + b_k8 * 16);

    float acc[2][4][2][4];
    #pragma unroll
    for (int i = 0; i < 2; i++)
        #pragma unroll
        for (int j = 0; j < 4; j++)
            #pragma unroll
            for (int k = 0; k < 2; k++)
                #pragma unroll
                for (int l = 0; l < 4; l++) acc[i][j][k][l] = 0.f;

    #pragma unroll
    for (int kc = 0; kc < 128; kc += 64) {
        const __nv_bfloat16* Ah = th_t + (size_t)r0 * 128 + kc;
        const __nv_bfloat16* Am = tm_t + (size_t)r0 * 128 + kc;
        #pragma unroll
        for (int it = 0; it < 4; ++it) {
            int idx = tid + it * 256;
            int row = idx >> 3, q = idx & 7;
            uint32_t so = (uint32_t)(row * A_STRB + q * 16);
            *(uint4*)(sAh + so) = __ldg((const uint4*)(Ah + (size_t)row * 128) + q);
            *(uint4*)(sAm + so) = __ldg((const uint4*)(Am + (size_t)row * 128) + q);
        }
        #pragma unroll
        for (int it = 0; it < 4; ++it) {
            int idx = tid + it * 256;
            int nr = idx >> 3, q = idx & 7;
            uint32_t so = (uint32_t)(nr * A_STRB + q * 16);
            *(uint4*)(sBh + so) = __ldg((const uint4*)(wth + nr * 1024 + kc0 + kc) + q);
            *(uint4*)(sBm + so) = __ldg((const uint4*)(wtm + nr * 1024 + kc0 + kc) + q);
        }
        __syncthreads();
        #pragma unroll
        for (int ks = 0; ks < 4; ++ks) {
            const uint32_t kso = ks * 32;
            uint32_t ah0[4], ah1[4], am0[4], am1[4];
            ldsm4(ah0, uAh + aoff0 + kso);
            ldsm4(ah1, uAh + aoff1 + kso);
            ldsm4(am0, uAm + aoff0 + kso);
            ldsm4(am1, uAm + aoff1 + kso);
            #pragma unroll
            for (int np = 0; np < 4; ++np) {
                const uint32_t bo = boffb + np * 16 * A_STRB + kso;
                uint32_t bh[4], bm[4];
                ldsm4(bh, uBh + bo);
                mma16816(acc[0][np][0], ah0, bh + 0);
                mma16816(acc[0][np][1], ah0, bh + 2);
                mma16816(acc[1][np][0], ah1, bh + 0);
                mma16816(acc[1][np][1], ah1, bh + 2);
                mma16816(acc[0][np][0], am0, bh + 0);
                mma16816(acc[0][np][1], am0, bh + 2);
                mma16816(acc[1][np][0], am1, bh + 0);
                mma16816(acc[1][np][1], am1, bh + 2);
                ldsm4(bm, uBm + bo);
                mma16816(acc[0][np][0], ah0, bm + 0);
                mma16816(acc[0][np][1], ah0, bm + 2);
                mma16816(acc[1][np][0], ah1, bm + 0);
                mma16816(acc[1][np][1], ah1, bm + 2);
            }
        }
        __syncthreads();
    }

    const int g = lane >> 2, t4 = lane & 3;
    #pragma unroll
    for (int mb = 0; mb < 2; ++mb) {
        int r = r0 + warp_m + mb * 16 + g;
        #pragma unroll
        for (int np = 0; np < 4; ++np) {
            #pragma unroll
            for (int blk = 0; blk < 2; ++blk) {
                int col = warp_n + np * 16 + blk * 8 + 2 * t4;
                float* a = acc[mb][np][blk];
                if (first) {
                    float b0 = __ldg(&bias[col]), b1 = __ldg(&bias[col + 1]);
                    if (r < n)
                        *(float2*)(out + (size_t)r * 128 + col) = make_float2(a[0] + b0, a[1] + b1);
                    if (r + 8 < n)
                        *(float2*)(out + (size_t)(r + 8) * 128 + col) = make_float2(a[2] + b0, a[3] + b1);
                } else {
                    if (r < n) {
                        float2 o = *(float2*)(out + (size_t)r * 128 + col);
                        *(float2*)(out + (size_t)r * 128 + col) = make_float2(o.x + a[0], o.y + a[1]);
                    }
                    if (r + 8 < n) {
                        float2 o = *(float2*)(out + (size_t)(r + 8) * 128 + col);
                        *(float2*)(out + (size_t)(r + 8) * 128 + col) = make_float2(o.x + a[2], o.y + a[3]);
                    }
                }
            }
        }
    }
}

// ---------------- launch ----------------
extern "C" void kernel_launch(void* const* d_in, const int* in_sizes, int n_in,
                              void* d_out, int out_size) {
    const float* input = (const float*)d_in[0];
    const int*   esrc  = (const int*)d_in[1];
    const int*   edst  = (const int*)d_in[2];
    const float* ew    = (const float*)d_in[3];
    const float* W     = (const float*)d_in[4];
    const float* bias  = (const float*)d_in[5];
    float*       out   = (float*)d_out;

    int n = in_sizes[0] / F;
    int e = in_sizes[1];

    float *bufA = nullptr, *bufB = nullptr;
    __nv_bfloat16 *th = nullptr, *tm = nullptr, *wth = nullptr, *wtm = nullptr;
    cudaGetSymbolAddress((void**)&bufA, g_bufA);
    cudaGetSymbolAddress((void**)&bufB, g_bufB);
    cudaGetSymbolAddress((void**)&th, g_termsh);
    cudaGetSymbolAddress((void**)&tm, g_termsm);
    cudaGetSymbolAddress((void**)&wth, g_wth);
    cudaGetSymbolAddress((void**)&wtm, g_wtm);

    static cudaStream_t s2 = nullptr;
    static cudaEvent_t ev[10];
    if (!s2) {
        cudaFuncSetAttribute(krylov_gemm_term, cudaFuncAttributeMaxDynamicSharedMemorySize, SM_GEMM);
        cudaStreamCreateWithFlags(&s2, cudaStreamNonBlocking);
        for (int i = 0; i < 10; ++i)
            cudaEventCreateWithFlags(&ev[i], cudaEventDisableTiming);
    }

    const int nb = (n + 1023) / 1024;
    const int gemm_blocks = (n + 127) / 128;

    // --- stream 0: prep that gemm0 needs, then fork gemm0 onto s2
    wprep_kernel<<<(1024 * 128 + 255) / 256, 256>>>(W);
    conv0_kernel<<<(n * 32 + 255) / 256, 256>>>(input, th, tm, n * 32);
    cudaEventRecord(ev[0], 0);
    cudaStreamWaitEvent(s2, ev[0], 0);
    krylov_gemm_term<<<gemm_blocks, 256, SM_GEMM, s2>>>(th, tm, wth, wtm, 0, bias, out, n, 1);

    // --- stream 0: CSR build (overlaps gemm0)
    zero_counts_kernel<<<(n + 255) / 256, 256>>>(n);
    hist_kernel<<<(e + 255) / 256, 256>>>(edst, e);
    scanA_kernel<<<nb, 1024>>>(n);
    scanB_kernel<<<1, 64>>>(nb);
    scanC_kernel<<<nb, 1024>>>(n);
    scatter_kernel<<<(e + 255) / 256, 256>>>(esrc, edst, ew, e);

    // --- Krylov chain on stream 0; per-term GEMM forked onto s2
    dim3 spmm_block(32, 8);
    int spmm_grid = (n + 7) / 8;
    const float* X = input;
    float* bufs[2] = {bufA, bufB};
    for (int t = 1; t < NBLK; ++t) {
        float* Y = bufs[t & 1];
        __nv_bfloat16* th_t = th + (size_t)t * NPAD * F;
        __nv_bfloat16* tm_t = tm + (size_t)t * NPAD * F;
        spmm_kernel<<<spmm_grid, spmm_block>>>(X, Y, th_t, tm_t, n);
        cudaEventRecord(ev[t], 0);
        cudaStreamWaitEvent(s2, ev[t], 0);
        krylov_gemm_term<<<gemm_blocks, 256, SM_GEMM, s2>>>(
            th_t, tm_t, wth, wtm, t * 128, bias, out, n, 0);
        X = Y;
    }

    // --- join s2 back into stream 0
    cudaEventRecord(ev[8], s2);
    cudaStreamWaitEvent(0, ev[8], 0);
}

// round 5
// speedup vs baseline: 1.1533x; 1.1533x over previous
#include <cuda_runtime.h>
#include <cuda_bf16.h>
#include <cstdint>

#define F 128
#define MAXN 50000
#define NPAD 50176
#define MAXE 800000
#define NBLK 8

// ---------------- device scratch ----------------
__device__ __nv_bfloat16 g_termsh[(size_t)NBLK * NPAD * F];
__device__ __nv_bfloat16 g_termsm[(size_t)NBLK * NPAD * F];
__device__ int   g_rowstart[MAXN + 1];
__device__ int   g_cnt[MAXN];
__device__ int   g_bsum[64];
__device__ int   g_boff[66];
__device__ int   g_csrs[MAXE];
__device__ float g_csrw[MAXE];
__device__ __nv_bfloat16 g_wth[F * NBLK * F];  // W^T hi  [128 n][1024 k]
__device__ __nv_bfloat16 g_wtm[F * NBLK * F];  // W^T mid

// ---------------- helpers ----------------
__device__ __forceinline__ uint32_t smem_u32(const void* p) {
    uint32_t a;
    asm("{ .reg .u64 t; cvta.to.shared.u64 t, %1; cvt.u32.u64 %0, t; }" : "=r"(a) : "l"(p));
    return a;
}
__device__ __forceinline__ void ldsm4(uint32_t* r, uint32_t addr) {
    asm volatile("ldmatrix.sync.aligned.m8n8.x4.shared.b16 {%0,%1,%2,%3}, [%4];"
        : "=r"(r[0]), "=r"(r[1]), "=r"(r[2]), "=r"(r[3]) : "r"(addr));
}
__device__ __forceinline__ void mma16816(float* c, const uint32_t* a, const uint32_t* b) {
    asm volatile("mma.sync.aligned.m16n8k16.row.col.f32.bf16.bf16.f32 "
        "{%0,%1,%2,%3}, {%4,%5,%6,%7}, {%8,%9}, {%0,%1,%2,%3};"
        : "+f"(c[0]), "+f"(c[1]), "+f"(c[2]), "+f"(c[3])
        : "r"(a[0]), "r"(a[1]), "r"(a[2]), "r"(a[3]), "r"(b[0]), "r"(b[1]));
}
__device__ __forceinline__ void split_bf16(float x, __nv_bfloat16& h, __nv_bfloat16& m) {
    h = __float2bfloat16_rn(x);
    m = __float2bfloat16_rn(x - __bfloat162float(h));
}
// unpack 2 bf16 (packed in u32) -> 2 floats
__device__ __forceinline__ float2 bf2f2(uint32_t u) {
    __nv_bfloat162 b = *(__nv_bfloat162*)&u;
    return make_float2(__bfloat162float(b.x), __bfloat162float(b.y));
}

// ---------------- CSR build ----------------
__global__ void zero_counts_kernel(int n) {
    int i = blockIdx.x * blockDim.x + threadIdx.x;
    if (i < n) g_cnt[i] = 0;
}
__global__ void hist_kernel(const int* __restrict__ edst, int e) {
    int i = blockIdx.x * blockDim.x + threadIdx.x;
    if (i < e) atomicAdd(&g_cnt[edst[i]], 1);
}
__global__ void scanA_kernel(int n) {
    __shared__ int wsum[32];
    int tid = threadIdx.x;
    int i = blockIdx.x * 1024 + tid;
    int v = (i < n) ? g_cnt[i] : 0;
    int lane = tid & 31, w = tid >> 5;
    int x = v;
    #pragma unroll
    for (int off = 1; off < 32; off <<= 1) {
        int t = __shfl_up_sync(0xffffffffu, x, off);
        if (lane >= off) x += t;
    }
    if (lane == 31) wsum[w] = x;
    __syncthreads();
    if (w == 0) {
        int s = wsum[lane];
        #pragma unroll
        for (int off = 1; off < 32; off <<= 1) {
            int t = __shfl_up_sync(0xffffffffu, s, off);
            if (lane >= off) s += t;
        }
        wsum[lane] = s;
    }
    __syncthreads();
    int base = (w > 0) ? wsum[w - 1] : 0;
    if (i < n) g_rowstart[i] = base + x - v;
    if (tid == 0) g_bsum[blockIdx.x] = wsum[31];
}
__global__ void scanB_kernel(int nb) {
    __shared__ int t0;
    int tid = threadIdx.x;  // 64
    int v = (tid < nb) ? g_bsum[tid] : 0;
    int lane = tid & 31, w = tid >> 5;
    int x = v;
    #pragma unroll
    for (int off = 1; off < 32; off <<= 1) {
        int t = __shfl_up_sync(0xffffffffu, x, off);
        if (lane >= off) x += t;
    }
    if (w == 0 && lane == 31) t0 = x;
    __syncthreads();
    int incl = x + (w ? t0 : 0);
    g_boff[tid] = incl - v;
    if (tid == 63) g_boff[64] = incl;
}
__global__ void scanC_kernel(int n) {
    int i = blockIdx.x * 1024 + threadIdx.x;
    if (i < n) {
        g_rowstart[i] += g_boff[blockIdx.x];
        g_cnt[i] = 0;
    }
    if (i == 0) g_rowstart[n] = g_boff[64];
}
__global__ void scatter_kernel(const int* __restrict__ esrc, const int* __restrict__ edst,
                               const float* __restrict__ ew, int e) {
    int i = blockIdx.x * blockDim.x + threadIdx.x;
    if (i < e) {
        int d = edst[i];
        int p = g_rowstart[d] + atomicAdd(&g_cnt[d], 1);
        g_csrs[p] = esrc[i];
        g_csrw[p] = ew[i];
    }
}

// ---------------- W^T split + term0 convert ----------------
__global__ void wprep_kernel(const float* __restrict__ W) {  // W [1024,128]
    int i = blockIdx.x * blockDim.x + threadIdx.x;
    if (i < 1024 * 128) {
        int k = i >> 7, nn = i & 127;
        __nv_bfloat16 h, m;
        split_bf16(W[i], h, m);
        g_wth[nn * 1024 + k] = h;
        g_wtm[nn * 1024 + k] = m;
    }
}
__global__ void conv0_kernel(const float* __restrict__ src,
                             __nv_bfloat16* __restrict__ th,
                             __nv_bfloat16* __restrict__ tm, int n4) {
    int i = blockIdx.x * blockDim.x + threadIdx.x;
    if (i >= n4) return;
    float4 x = ((const float4*)src)[i];
    __nv_bfloat16 h[4], m[4];
    split_bf16(x.x, h[0], m[0]); split_bf16(x.y, h[1], m[1]);
    split_bf16(x.z, h[2], m[2]); split_bf16(x.w, h[3], m[3]);
    int node = i >> 5, q = i & 31;
    size_t off = (size_t)node * 128 + q * 4;
    *(uint2*)&th[off] = *(uint2*)h;
    *(uint2*)&tm[off] = *(uint2*)m;
}

// ---------------- SpMM on bf16 h/m terms: Yhm[t] = A @ (h+m)[t-1] ----------------
__global__ void spmm_kernel(const __nv_bfloat16* __restrict__ xh,
                            const __nv_bfloat16* __restrict__ xm,
                            __nv_bfloat16* __restrict__ yh,
                            __nv_bfloat16* __restrict__ ym, int n) {
    int node = blockIdx.x * blockDim.y + threadIdx.y;
    if (node >= n) return;
    int lane = threadIdx.x;
    int p = g_rowstart[node], end = g_rowstart[node + 1];
    float4 acc = make_float4(0.f, 0.f, 0.f, 0.f);
    const uint2* Hv = (const uint2*)xh;   // 4 bf16 per uint2
    const uint2* Mv = (const uint2*)xm;
    for (; p + 4 <= end; p += 4) {
        int s0 = __ldg(&g_csrs[p]),     s1 = __ldg(&g_csrs[p + 1]);
        int s2 = __ldg(&g_csrs[p + 2]), s3 = __ldg(&g_csrs[p + 3]);
        float w0 = __ldg(&g_csrw[p]),     w1 = __ldg(&g_csrw[p + 1]);
        float w2 = __ldg(&g_csrw[p + 2]), w3 = __ldg(&g_csrw[p + 3]);
        uint2 h0 = __ldg(&Hv[s0 * 32 + lane]), m0 = __ldg(&Mv[s0 * 32 + lane]);
        uint2 h1 = __ldg(&Hv[s1 * 32 + lane]), m1 = __ldg(&Mv[s1 * 32 + lane]);
        uint2 h2 = __ldg(&Hv[s2 * 32 + lane]), m2 = __ldg(&Mv[s2 * 32 + lane]);
        uint2 h3 = __ldg(&Hv[s3 * 32 + lane]), m3 = __ldg(&Mv[s3 * 32 + lane]);
        float2 a, b;
        a = bf2f2(h0.x); b = bf2f2(m0.x); acc.x += w0 * (a.x + b.x); acc.y += w0 * (a.y + b.y);
        a = bf2f2(h0.y); b = bf2f2(m0.y); acc.z += w0 * (a.x + b.x); acc.w += w0 * (a.y + b.y);
        a = bf2f2(h1.x); b = bf2f2(m1.x); acc.x += w1 * (a.x + b.x); acc.y += w1 * (a.y + b.y);
        a = bf2f2(h1.y); b = bf2f2(m1.y); acc.z += w1 * (a.x + b.x); acc.w += w1 * (a.y + b.y);
        a = bf2f2(h2.x); b = bf2f2(m2.x); acc.x += w2 * (a.x + b.x); acc.y += w2 * (a.y + b.y);
        a = bf2f2(h2.y); b = bf2f2(m2.y); acc.z += w2 * (a.x + b.x); acc.w += w2 * (a.y + b.y);
        a = bf2f2(h3.x); b = bf2f2(m3.x); acc.x += w3 * (a.x + b.x); acc.y += w3 * (a.y + b.y);
        a = bf2f2(h3.y); b = bf2f2(m3.y); acc.z += w3 * (a.x + b.x); acc.w += w3 * (a.y + b.y);
    }
    for (; p < end; ++p) {
        int s = __ldg(&g_csrs[p]);
        float w = __ldg(&g_csrw[p]);
        uint2 hv = __ldg(&Hv[s * 32 + lane]), mv = __ldg(&Mv[s * 32 + lane]);
        float2 a, b;
        a = bf2f2(hv.x); b = bf2f2(mv.x); acc.x += w * (a.x + b.x); acc.y += w * (a.y + b.y);
        a = bf2f2(hv.y); b = bf2f2(mv.y); acc.z += w * (a.x + b.x); acc.w += w * (a.y + b.y);
    }
    __nv_bfloat16 h[4], m[4];
    split_bf16(acc.x, h[0], m[0]); split_bf16(acc.y, h[1], m[1]);
    split_bf16(acc.z, h[2], m[2]); split_bf16(acc.w, h[3], m[3]);
    size_t off = (size_t)node * 128 + lane * 4;
    *(uint2*)&yh[off] = *(uint2*)h;
    *(uint2*)&ym[off] = *(uint2*)m;
}

// ---------------- GEMM: out[N,128] = cat[N,1024] @ W[1024,128] + bias ----------------
#define A_STRB 144
#define TILE_BYTES (128 * A_STRB)
#define SM_GEMM (4 * TILE_BYTES)

__global__ void __launch_bounds__(256, 2) krylov_gemm(
    const __nv_bfloat16* __restrict__ th, const __nv_bfloat16* __restrict__ tm,
    const __nv_bfloat16* __restrict__ wth, const __nv_bfloat16* __restrict__ wtm,
    const float* __restrict__ bias, float* __restrict__ out, int n)
{
    extern __shared__ char smem[];
    char* sAh = smem;
    char* sAm = smem + TILE_BYTES;
    char* sBh = smem + 2 * TILE_BYTES;
    char* sBm = smem + 3 * TILE_BYTES;
    const uint32_t uAh = smem_u32(sAh), uAm = smem_u32(sAm);
    const uint32_t uBh = smem_u32(sBh), uBm = smem_u32(sBm);

    const int tid = threadIdx.x, lane = tid & 31, wid = tid >> 5;
    const int warp_m = (wid & 3) * 32;
    const int warp_n = (wid >> 2) * 64;
    const int r0 = blockIdx.x * 128;

    const int a_rin = (lane & 7) + ((lane >> 3) & 1) * 8;
    const int a_k8  = (lane >> 4);
    const int b_nrow = (lane & 7) + (lane >> 4) * 8;
    const int b_k8   = (lane >> 3) & 1;
    const uint32_t aoff0 = (uint32_t)((warp_m + a_rin) * A_STRB + a_k8 * 16);
    const uint32_t aoff1 = aoff0 + 16 * A_STRB;
    const uint32_t boffb = (uint32_t)((warp_n + b_nrow) * A_STRB + b_k8 * 16);

    float acc[2][4][2][4];
    #pragma unroll
    for (int i = 0; i < 2; i++)
        #pragma unroll
        for (int j = 0; j < 4; j++)
            #pragma unroll
            for (int k = 0; k < 2; k++)
                #pragma unroll
                for (int l = 0; l < 4; l++) acc[i][j][k][l] = 0.f;

    for (int kc = 0; kc < 1024; kc += 64) {
        const int term = kc >> 7;
        const int col0 = kc & 127;
        const __nv_bfloat16* Ah = th + ((size_t)term * NPAD + r0) * 128 + col0;
        const __nv_bfloat16* Am = tm + ((size_t)term * NPAD + r0) * 128 + col0;
        #pragma unroll
        for (int it = 0; it < 4; ++it) {
            int idx = tid + it * 256;
            int row = idx >> 3, q = idx & 7;
            uint32_t so = (uint32_t)(row * A_STRB + q * 16);
            *(uint4*)(sAh + so) = __ldg((const uint4*)(Ah + (size_t)row * 128) + q);
            *(uint4*)(sAm + so) = __ldg((const uint4*)(Am + (size_t)row * 128) + q);
        }
        #pragma unroll
        for (int it = 0; it < 4; ++it) {
            int idx = tid + it * 256;
            int nr = idx >> 3, q = idx & 7;
            uint32_t so = (uint32_t)(nr * A_STRB + q * 16);
            *(uint4*)(sBh + so) = __ldg((const uint4*)(wth + nr * 1024 + kc) + q);
            *(uint4*)(sBm + so) = __ldg((const uint4*)(wtm + nr * 1024 + kc) + q);
        }
        __syncthreads();
        #pragma unroll
        for (int ks = 0; ks < 4; ++ks) {
            const uint32_t kso = ks * 32;
            uint32_t ah0[4], ah1[4], am0[4], am1[4];
            ldsm4(ah0, uAh + aoff0 + kso);
            ldsm4(ah1, uAh + aoff1 + kso);
            ldsm4(am0, uAm + aoff0 + kso);
            ldsm4(am1, uAm + aoff1 + kso);
            #pragma unroll
            for (int np = 0; np < 4; ++np) {
                const uint32_t bo = boffb + np * 16 * A_STRB + kso;
                uint32_t bh[4], bm[4];
                ldsm4(bh, uBh + bo);
                mma16816(acc[0][np][0], ah0, bh + 0);
                mma16816(acc[0][np][1], ah0, bh + 2);
                mma16816(acc[1][np][0], ah1, bh + 0);
                mma16816(acc[1][np][1], ah1, bh + 2);
                mma16816(acc[0][np][0], am0, bh + 0);
                mma16816(acc[0][np][1], am0, bh + 2);
                mma16816(acc[1][np][0], am1, bh + 0);
                mma16816(acc[1][np][1], am1, bh + 2);
                ldsm4(bm, uBm + bo);
                mma16816(acc[0][np][0], ah0, bm + 0);
                mma16816(acc[0][np][1], ah0, bm + 2);
                mma16816(acc[1][np][0], ah1, bm + 0);
                mma16816(acc[1][np][1], ah1, bm + 2);
            }
        }
        __syncthreads();
    }

    const int g = lane >> 2, t4 = lane & 3;
    #pragma unroll
    for (int mb = 0; mb < 2; ++mb) {
        int r = r0 + warp_m + mb * 16 + g;
        #pragma unroll
        for (int np = 0; np < 4; ++np) {
            #pragma unroll
            for (int blk = 0; blk < 2; ++blk) {
                int col = warp_n + np * 16 + blk * 8 + 2 * t4;
                float b0 = __ldg(&bias[col]), b1 = __ldg(&bias[col + 1]);
                float* a = acc[mb][np][blk];
                if (r < n)
                    *(float2*)(out + (size_t)r * 128 + col) = make_float2(a[0] + b0, a[1] + b1);
                if (r + 8 < n)
                    *(float2*)(out + (size_t)(r + 8) * 128 + col) = make_float2(a[2] + b0, a[3] + b1);
            }
        }
    }
}

// ---------------- launch ----------------
extern "C" void kernel_launch(void* const* d_in, const int* in_sizes, int n_in,
                              void* d_out, int out_size) {
    const float* input = (const float*)d_in[0];
    const int*   esrc  = (const int*)d_in[1];
    const int*   edst  = (const int*)d_in[2];
    const float* ew    = (const float*)d_in[3];
    const float* W     = (const float*)d_in[4];
    const float* bias  = (const float*)d_in[5];
    float*       out   = (float*)d_out;

    int n = in_sizes[0] / F;
    int e = in_sizes[1];

    __nv_bfloat16 *th = nullptr, *tm = nullptr, *wth = nullptr, *wtm = nullptr;
    cudaGetSymbolAddress((void**)&th, g_termsh);
    cudaGetSymbolAddress((void**)&tm, g_termsm);
    cudaGetSymbolAddress((void**)&wth, g_wth);
    cudaGetSymbolAddress((void**)&wtm, g_wtm);

    cudaFuncSetAttribute(krylov_gemm, cudaFuncAttributeMaxDynamicSharedMemorySize, SM_GEMM);

    const int nb = (n + 1023) / 1024;

    // 1) CSR build (hierarchical scan)
    zero_counts_kernel<<<(n + 255) / 256, 256>>>(n);
    hist_kernel<<<(e + 255) / 256, 256>>>(edst, e);
    scanA_kernel<<<nb, 1024>>>(n);
    scanB_kernel<<<1, 64>>>(nb);
    scanC_kernel<<<nb, 1024>>>(n);
    scatter_kernel<<<(e + 255) / 256, 256>>>(esrc, edst, ew, e);

    // 2) W^T bf16 hi/mid + term0 conversion
    wprep_kernel<<<(1024 * 128 + 255) / 256, 256>>>(W);
    conv0_kernel<<<(n * 32 + 255) / 256, 256>>>(input, th, tm, n * 32);

    // 3) Krylov chain entirely in bf16 h/m
    dim3 spmm_block(32, 8);
    int spmm_grid = (n + 7) / 8;
    for (int t = 1; t < NBLK; ++t) {
        const __nv_bfloat16* xh = th + (size_t)(t - 1) * NPAD * F;
        const __nv_bfloat16* xm = tm + (size_t)(t - 1) * NPAD * F;
        __nv_bfloat16* yh = th + (size_t)t * NPAD * F;
        __nv_bfloat16* ym = tm + (size_t)t * NPAD * F;
        spmm_kernel<<<spmm_grid, spmm_block>>>(xh, xm, yh, ym, n);
    }

    // 4) single tensor-core GEMM + bias
    krylov_gemm<<<(n + 127) / 128, 256, SM_GEMM>>>(th, tm, wth, wtm, bias, out, n);
}

// round 6
// speedup vs baseline: 1.2803x; 1.1101x over previous
#include <cuda_runtime.h>
#include <cuda_bf16.h>
#include <cstdint>

#define F 128
#define MAXN 50000
#define NPAD 50176
#define MAXE 800000
#define NBLK 8

// ---------------- device scratch ----------------
__device__ float g_bufA[MAXN * F];
__device__ float g_bufB[MAXN * F];
__device__ __nv_bfloat16 g_termsh[(size_t)NBLK * NPAD * F];
__device__ __nv_bfloat16 g_termsm[(size_t)NBLK * NPAD * F];
__device__ int   g_rowstart[MAXN + 1];
__device__ int   g_cnt[MAXN];
__device__ int   g_bsum[64];
__device__ int   g_boff[66];
__device__ int   g_csrs[MAXE];
__device__ float g_csrw[MAXE];
__device__ __nv_bfloat16 g_wth[F * NBLK * F];  // W^T hi  [128 n][1024 k]
__device__ __nv_bfloat16 g_wtm[F * NBLK * F];  // W^T mid

// ---------------- helpers ----------------
__device__ __forceinline__ uint32_t smem_u32(const void* p) {
    uint32_t a;
    asm("{ .reg .u64 t; cvta.to.shared.u64 t, %1; cvt.u32.u64 %0, t; }" : "=r"(a) : "l"(p));
    return a;
}
__device__ __forceinline__ void ldsm4(uint32_t* r, uint32_t addr) {
    asm volatile("ldmatrix.sync.aligned.m8n8.x4.shared.b16 {%0,%1,%2,%3}, [%4];"
        : "=r"(r[0]), "=r"(r[1]), "=r"(r[2]), "=r"(r[3]) : "r"(addr));
}
__device__ __forceinline__ void mma16816(float* c, const uint32_t* a, const uint32_t* b) {
    asm volatile("mma.sync.aligned.m16n8k16.row.col.f32.bf16.bf16.f32 "
        "{%0,%1,%2,%3}, {%4,%5,%6,%7}, {%8,%9}, {%0,%1,%2,%3};"
        : "+f"(c[0]), "+f"(c[1]), "+f"(c[2]), "+f"(c[3])
        : "r"(a[0]), "r"(a[1]), "r"(a[2]), "r"(a[3]), "r"(b[0]), "r"(b[1]));
}
__device__ __forceinline__ void split_bf16(float x, __nv_bfloat16& h, __nv_bfloat16& m) {
    h = __float2bfloat16_rn(x);
    m = __float2bfloat16_rn(x - __bfloat162float(h));
}

// ---------------- CSR build ----------------
__global__ void zero_counts_kernel(int n) {
    int i = blockIdx.x * blockDim.x + threadIdx.x;
    if (i < n) g_cnt[i] = 0;
}
__global__ void hist_kernel(const int* __restrict__ edst, int e) {
    int i = blockIdx.x * blockDim.x + threadIdx.x;
    if (i < e) atomicAdd(&g_cnt[edst[i]], 1);
}
__global__ void scanA_kernel(int n) {
    __shared__ int wsum[32];
    int tid = threadIdx.x;
    int i = blockIdx.x * 1024 + tid;
    int v = (i < n) ? g_cnt[i] : 0;
    int lane = tid & 31, w = tid >> 5;
    int x = v;
    #pragma unroll
    for (int off = 1; off < 32; off <<= 1) {
        int t = __shfl_up_sync(0xffffffffu, x, off);
        if (lane >= off) x += t;
    }
    if (lane == 31) wsum[w] = x;
    __syncthreads();
    if (w == 0) {
        int s = wsum[lane];
        #pragma unroll
        for (int off = 1; off < 32; off <<= 1) {
            int t = __shfl_up_sync(0xffffffffu, s, off);
            if (lane >= off) s += t;
        }
        wsum[lane] = s;
    }
    __syncthreads();
    int base = (w > 0) ? wsum[w - 1] : 0;
    if (i < n) g_rowstart[i] = base + x - v;
    if (tid == 0) g_bsum[blockIdx.x] = wsum[31];
}
__global__ void scanB_kernel(int nb) {
    __shared__ int t0;
    int tid = threadIdx.x;  // 64
    int v = (tid < nb) ? g_bsum[tid] : 0;
    int lane = tid & 31, w = tid >> 5;
    int x = v;
    #pragma unroll
    for (int off = 1; off < 32; off <<= 1) {
        int t = __shfl_up_sync(0xffffffffu, x, off);
        if (lane >= off) x += t;
    }
    if (w == 0 && lane == 31) t0 = x;
    __syncthreads();
    int incl = x + (w ? t0 : 0);
    g_boff[tid] = incl - v;
    if (tid == 63) g_boff[64] = incl;
}
__global__ void scanC_kernel(int n) {
    int i = blockIdx.x * 1024 + threadIdx.x;
    if (i < n) {
        g_rowstart[i] += g_boff[blockIdx.x];
        g_cnt[i] = 0;
    }
    if (i == 0) g_rowstart[n] = g_boff[64];
}
__global__ void scatter_kernel(const int* __restrict__ esrc, const int* __restrict__ edst,
                               const float* __restrict__ ew, int e) {
    int i = blockIdx.x * blockDim.x + threadIdx.x;
    if (i < e) {
        int d = edst[i];
        int p = g_rowstart[d] + atomicAdd(&g_cnt[d], 1);
        g_csrs[p] = esrc[i];
        g_csrw[p] = ew[i];
    }
}

// ---------------- W^T split + term0 convert ----------------
__global__ void wprep_kernel(const float* __restrict__ W) {  // W [1024,128]
    int i = blockIdx.x * blockDim.x + threadIdx.x;
    if (i < 1024 * 128) {
        int k = i >> 7, nn = i & 127;
        __nv_bfloat16 h, m;
        split_bf16(W[i], h, m);
        g_wth[nn * 1024 + k] = h;
        g_wtm[nn * 1024 + k] = m;
    }
}
__global__ void conv0_kernel(const float* __restrict__ src,
                             __nv_bfloat16* __restrict__ th,
                             __nv_bfloat16* __restrict__ tm, int n4) {
    int i = blockIdx.x * blockDim.x + threadIdx.x;
    if (i >= n4) return;
    float4 x = ((const float4*)src)[i];
    __nv_bfloat16 h[4], m[4];
    split_bf16(x.x, h[0], m[0]); split_bf16(x.y, h[1], m[1]);
    split_bf16(x.z, h[2], m[2]); split_bf16(x.w, h[3], m[3]);
    int node = i >> 5, q = i & 31;
    size_t off = (size_t)node * 128 + q * 4;
    *(uint2*)&th[off] = *(uint2*)h;
    *(uint2*)&tm[off] = *(uint2*)m;
}

// ---------------- SpMM: fp32 gather, unroll-4, emits fp32 Y + bf16 h/m ----------------
__global__ void spmm_kernel(const float* __restrict__ X, float* __restrict__ Y,
                            __nv_bfloat16* __restrict__ th,
                            __nv_bfloat16* __restrict__ tm, int n) {
    int node = blockIdx.x * blockDim.y + threadIdx.y;
    if (node >= n) return;
    int lane = threadIdx.x;
    int p = g_rowstart[node], end = g_rowstart[node + 1];
    float4 acc = make_float4(0.f, 0.f, 0.f, 0.f);
    const float4* Xv = (const float4*)X;
    for (; p + 4 <= end; p += 4) {
        int s0 = __ldg(&g_csrs[p]),     s1 = __ldg(&g_csrs[p + 1]);
        int s2 = __ldg(&g_csrs[p + 2]), s3 = __ldg(&g_csrs[p + 3]);
        float w0 = __ldg(&g_csrw[p]),     w1 = __ldg(&g_csrw[p + 1]);
        float w2 = __ldg(&g_csrw[p + 2]), w3 = __ldg(&g_csrw[p + 3]);
        float4 x0 = __ldg(&Xv[s0 * 32 + lane]);
        float4 x1 = __ldg(&Xv[s1 * 32 + lane]);
        float4 x2 = __ldg(&Xv[s2 * 32 + lane]);
        float4 x3 = __ldg(&Xv[s3 * 32 + lane]);
        acc.x += w0 * x0.x + w1 * x1.x + w2 * x2.x + w3 * x3.x;
        acc.y += w0 * x0.y + w1 * x1.y + w2 * x2.y + w3 * x3.y;
        acc.z += w0 * x0.z + w1 * x1.z + w2 * x2.z + w3 * x3.z;
        acc.w += w0 * x0.w + w1 * x1.w + w2 * x2.w + w3 * x3.w;
    }
    for (; p < end; ++p) {
        int s = __ldg(&g_csrs[p]);
        float w = __ldg(&g_csrw[p]);
        float4 x = __ldg(&Xv[s * 32 + lane]);
        acc.x += w * x.x; acc.y += w * x.y; acc.z += w * x.z; acc.w += w * x.w;
    }
    ((float4*)Y)[node * 32 + lane] = acc;
    __nv_bfloat16 h[4], m[4];
    split_bf16(acc.x, h[0], m[0]); split_bf16(acc.y, h[1], m[1]);
    split_bf16(acc.z, h[2], m[2]); split_bf16(acc.w, h[3], m[3]);
    size_t off = (size_t)node * 128 + lane * 4;
    *(uint2*)&th[off] = *(uint2*)h;
    *(uint2*)&tm[off] = *(uint2*)m;
}

// ---------------- GEMM: out[N,128] = cat[N,1024] @ W[1024,128] + bias ----------------
#define A_STRB 144
#define TILE_BYTES (128 * A_STRB)
#define SM_GEMM (4 * TILE_BYTES)

__global__ void __launch_bounds__(256, 2) krylov_gemm(
    const __nv_bfloat16* __restrict__ th, const __nv_bfloat16* __restrict__ tm,
    const __nv_bfloat16* __restrict__ wth, const __nv_bfloat16* __restrict__ wtm,
    const float* __restrict__ bias, float* __restrict__ out, int n)
{
    extern __shared__ char smem[];
    char* sAh = smem;
    char* sAm = smem + TILE_BYTES;
    char* sBh = smem + 2 * TILE_BYTES;
    char* sBm = smem + 3 * TILE_BYTES;
    const uint32_t uAh = smem_u32(sAh), uAm = smem_u32(sAm);
    const uint32_t uBh = smem_u32(sBh), uBm = smem_u32(sBm);

    const int tid = threadIdx.x, lane = tid & 31, wid = tid >> 5;
    const int warp_m = (wid & 3) * 32;
    const int warp_n = (wid >> 2) * 64;
    const int r0 = blockIdx.x * 128;

    const int a_rin = (lane & 7) + ((lane >> 3) & 1) * 8;
    const int a_k8  = (lane >> 4);
    const int b_nrow = (lane & 7) + (lane >> 4) * 8;
    const int b_k8   = (lane >> 3) & 1;
    const uint32_t aoff0 = (uint32_t)((warp_m + a_rin) * A_STRB + a_k8 * 16);
    const uint32_t aoff1 = aoff0 + 16 * A_STRB;
    const uint32_t boffb = (uint32_t)((warp_n + b_nrow) * A_STRB + b_k8 * 16);

    float acc[2][4][2][4];
    #pragma unroll
    for (int i = 0; i < 2; i++)
        #pragma unroll
        for (int j = 0; j < 4; j++)
            #pragma unroll
            for (int k = 0; k < 2; k++)
                #pragma unroll
                for (int l = 0; l < 4; l++) acc[i][j][k][l] = 0.f;

    for (int kc = 0; kc < 1024; kc += 64) {
        const int term = kc >> 7;
        const int col0 = kc & 127;
        const __nv_bfloat16* Ah = th + ((size_t)term * NPAD + r0) * 128 + col0;
        const __nv_bfloat16* Am = tm + ((size_t)term * NPAD + r0) * 128 + col0;
        #pragma unroll
        for (int it = 0; it < 4; ++it) {
            int idx = tid + it * 256;
            int row = idx >> 3, q = idx & 7;
            uint32_t so = (uint32_t)(row * A_STRB + q * 16);
            *(uint4*)(sAh + so) = __ldg((const uint4*)(Ah + (size_t)row * 128) + q);
            *(uint4*)(sAm + so) = __ldg((const uint4*)(Am + (size_t)row * 128) + q);
        }
        #pragma unroll
        for (int it = 0; it < 4; ++it) {
            int idx = tid + it * 256;
            int nr = idx >> 3, q = idx & 7;
            uint32_t so = (uint32_t)(nr * A_STRB + q * 16);
            *(uint4*)(sBh + so) = __ldg((const uint4*)(wth + nr * 1024 + kc) + q);
            *(uint4*)(sBm + so) = __ldg((const uint4*)(wtm + nr * 1024 + kc) + q);
        }
        __syncthreads();
        #pragma unroll
        for (int ks = 0; ks < 4; ++ks) {
            const uint32_t kso = ks * 32;
            uint32_t ah0[4], ah1[4], am0[4], am1[4];
            ldsm4(ah0, uAh + aoff0 + kso);
            ldsm4(ah1, uAh + aoff1 + kso);
            ldsm4(am0, uAm + aoff0 + kso);
            ldsm4(am1, uAm + aoff1 + kso);
            #pragma unroll
            for (int np = 0; np < 4; ++np) {
                const uint32_t bo = boffb + np * 16 * A_STRB + kso;
                uint32_t bh[4], bm[4];
                ldsm4(bh, uBh + bo);
                mma16816(acc[0][np][0], ah0, bh + 0);
                mma16816(acc[0][np][1], ah0, bh + 2);
                mma16816(acc[1][np][0], ah1, bh + 0);
                mma16816(acc[1][np][1], ah1, bh + 2);
                mma16816(acc[0][np][0], am0, bh + 0);
                mma16816(acc[0][np][1], am0, bh + 2);
                mma16816(acc[1][np][0], am1, bh + 0);
                mma16816(acc[1][np][1], am1, bh + 2);
                ldsm4(bm, uBm + bo);
                mma16816(acc[0][np][0], ah0, bm + 0);
                mma16816(acc[0][np][1], ah0, bm + 2);
                mma16816(acc[1][np][0], ah1, bm + 0);
                mma16816(acc[1][np][1], ah1, bm + 2);
            }
        }
        __syncthreads();
    }

    const int g = lane >> 2, t4 = lane & 3;
    #pragma unroll
    for (int mb = 0; mb < 2; ++mb) {
        int r = r0 + warp_m + mb * 16 + g;
        #pragma unroll
        for (int np = 0; np < 4; ++np) {
            #pragma unroll
            for (int blk = 0; blk < 2; ++blk) {
                int col = warp_n + np * 16 + blk * 8 + 2 * t4;
                float b0 = __ldg(&bias[col]), b1 = __ldg(&bias[col + 1]);
                float* a = acc[mb][np][blk];
                if (r < n)
                    *(float2*)(out + (size_t)r * 128 + col) = make_float2(a[0] + b0, a[1] + b1);
                if (r + 8 < n)
                    *(float2*)(out + (size_t)(r + 8) * 128 + col) = make_float2(a[2] + b0, a[3] + b1);
            }
        }
    }
}

// ---------------- launch ----------------
extern "C" void kernel_launch(void* const* d_in, const int* in_sizes, int n_in,
                              void* d_out, int out_size) {
    const float* input = (const float*)d_in[0];
    const int*   esrc  = (const int*)d_in[1];
    const int*   edst  = (const int*)d_in[2];
    const float* ew    = (const float*)d_in[3];
    const float* W     = (const float*)d_in[4];
    const float* bias  = (const float*)d_in[5];
    float*       out   = (float*)d_out;

    int n = in_sizes[0] / F;
    int e = in_sizes[1];

    float *bufA = nullptr, *bufB = nullptr;
    __nv_bfloat16 *th = nullptr, *tm = nullptr, *wth = nullptr, *wtm = nullptr;
    cudaGetSymbolAddress((void**)&bufA, g_bufA);
    cudaGetSymbolAddress((void**)&bufB, g_bufB);
    cudaGetSymbolAddress((void**)&th, g_termsh);
    cudaGetSymbolAddress((void**)&tm, g_termsm);
    cudaGetSymbolAddress((void**)&wth, g_wth);
    cudaGetSymbolAddress((void**)&wtm, g_wtm);

    static cudaStream_t s2 = nullptr;
    static cudaEvent_t ev0, ev1;
    if (!s2) {
        cudaFuncSetAttribute(krylov_gemm, cudaFuncAttributeMaxDynamicSharedMemorySize, SM_GEMM);
        cudaStreamCreateWithFlags(&s2, cudaStreamNonBlocking);
        cudaEventCreateWithFlags(&ev0, cudaEventDisableTiming);
        cudaEventCreateWithFlags(&ev1, cudaEventDisableTiming);
    }

    const int nb = (n + 1023) / 1024;

    // fork: CSR build (latency-bound) on s2, concurrent with W/term0 prep (bandwidth)
    cudaEventRecord(ev0, 0);
    cudaStreamWaitEvent(s2, ev0, 0);
    zero_counts_kernel<<<(n + 255) / 256, 256, 0, s2>>>(n);
    hist_kernel<<<(e + 255) / 256, 256, 0, s2>>>(edst, e);
    scanA_kernel<<<nb, 1024, 0, s2>>>(n);
    scanB_kernel<<<1, 64, 0, s2>>>(nb);
    scanC_kernel<<<nb, 1024, 0, s2>>>(n);
    scatter_kernel<<<(e + 255) / 256, 256, 0, s2>>>(esrc, edst, ew, e);

    wprep_kernel<<<(1024 * 128 + 255) / 256, 256>>>(W);
    conv0_kernel<<<(n * 32 + 255) / 256, 256>>>(input, th, tm, n * 32);

    // join
    cudaEventRecord(ev1, s2);
    cudaStreamWaitEvent(0, ev1, 0);

    // Krylov chain: fp32 ping-pong, bf16 h/m emitted per term
    dim3 spmm_block(32, 8);
    int spmm_grid = (n + 7) / 8;
    const float* X = input;
    float* bufs[2] = {bufA, bufB};
    for (int t = 1; t < NBLK; ++t) {
        float* Y = bufs[t & 1];
        spmm_kernel<<<spmm_grid, spmm_block>>>(X, Y,
            th + (size_t)t * NPAD * F, tm + (size_t)t * NPAD * F, n);
        X = Y;
    }

    // single tensor-core GEMM + bias
    krylov_gemm<<<(n + 127) / 128, 256, SM_GEMM>>>(th, tm, wth, wtm, bias, out, n);
}

// round 7
// speedup vs baseline: 1.7174x; 1.3415x over previous
#include <cuda_runtime.h>
#include <cuda_fp16.h>
#include <cstdint>

#define F 128
#define MAXN 50000
#define NPAD 50176
#define MAXE 800000
#define NBLK 8

// ---------------- device scratch ----------------
__device__ __half g_terms[(size_t)NBLK * NPAD * F];   // fp16 Krylov terms (~103MB)
__device__ int    g_rowstart[MAXN + 1];
__device__ int    g_cnt[MAXN];
__device__ int    g_bsum[64];
__device__ int    g_boff[66];
__device__ int    g_csrs[MAXE];
__device__ float  g_csrw[MAXE];
__device__ __half g_wth[F * NBLK * F];  // W^T hi  [128 n][1024 k] fp16
__device__ __half g_wtm[F * NBLK * F];  // W^T mid

// ---------------- helpers ----------------
__device__ __forceinline__ uint32_t smem_u32(const void* p) {
    uint32_t a;
    asm("{ .reg .u64 t; cvta.to.shared.u64 t, %1; cvt.u32.u64 %0, t; }" : "=r"(a) : "l"(p));
    return a;
}
__device__ __forceinline__ void ldsm4(uint32_t* r, uint32_t addr) {
    asm volatile("ldmatrix.sync.aligned.m8n8.x4.shared.b16 {%0,%1,%2,%3}, [%4];"
        : "=r"(r[0]), "=r"(r[1]), "=r"(r[2]), "=r"(r[3]) : "r"(addr));
}
__device__ __forceinline__ void mma16816(float* c, const uint32_t* a, const uint32_t* b) {
    asm volatile("mma.sync.aligned.m16n8k16.row.col.f32.f16.f16.f32 "
        "{%0,%1,%2,%3}, {%4,%5,%6,%7}, {%8,%9}, {%0,%1,%2,%3};"
        : "+f"(c[0]), "+f"(c[1]), "+f"(c[2]), "+f"(c[3])
        : "r"(a[0]), "r"(a[1]), "r"(a[2]), "r"(a[3]), "r"(b[0]), "r"(b[1]));
}
__device__ __forceinline__ void split_f16(float x, __half& h, __half& m) {
    h = __float2half_rn(x);
    m = __float2half_rn(x - __half2float(h));
}

// ---------------- CSR build ----------------
__global__ void zero_counts_kernel(int n) {
    int i = blockIdx.x * blockDim.x + threadIdx.x;
    if (i < n) g_cnt[i] = 0;
}
__global__ void hist_kernel(const int* __restrict__ edst, int e) {
    int i = blockIdx.x * blockDim.x + threadIdx.x;
    if (i < e) atomicAdd(&g_cnt[edst[i]], 1);
}
__global__ void scanA_kernel(int n) {
    __shared__ int wsum[32];
    int tid = threadIdx.x;
    int i = blockIdx.x * 1024 + tid;
    int v = (i < n) ? g_cnt[i] : 0;
    int lane = tid & 31, w = tid >> 5;
    int x = v;
    #pragma unroll
    for (int off = 1; off < 32; off <<= 1) {
        int t = __shfl_up_sync(0xffffffffu, x, off);
        if (lane >= off) x += t;
    }
    if (lane == 31) wsum[w] = x;
    __syncthreads();
    if (w == 0) {
        int s = wsum[lane];
        #pragma unroll
        for (int off = 1; off < 32; off <<= 1) {
            int t = __shfl_up_sync(0xffffffffu, s, off);
            if (lane >= off) s += t;
        }
        wsum[lane] = s;
    }
    __syncthreads();
    int base = (w > 0) ? wsum[w - 1] : 0;
    if (i < n) g_rowstart[i] = base + x - v;
    if (tid == 0) g_bsum[blockIdx.x] = wsum[31];
}
__global__ void scanB_kernel(int nb) {
    __shared__ int t0;
    int tid = threadIdx.x;  // 64
    int v = (tid < nb) ? g_bsum[tid] : 0;
    int lane = tid & 31, w = tid >> 5;
    int x = v;
    #pragma unroll
    for (int off = 1; off < 32; off <<= 1) {
        int t = __shfl_up_sync(0xffffffffu, x, off);
        if (lane >= off) x += t;
    }
    if (w == 0 && lane == 31) t0 = x;
    __syncthreads();
    int incl = x + (w ? t0 : 0);
    g_boff[tid] = incl - v;
    if (tid == 63) g_boff[64] = incl;
}
__global__ void scanC_kernel(int n) {
    int i = blockIdx.x * 1024 + threadIdx.x;
    if (i < n) {
        g_rowstart[i] += g_boff[blockIdx.x];
        g_cnt[i] = 0;
    }
    if (i == 0) g_rowstart[n] = g_boff[64];
}
__global__ void scatter_kernel(const int* __restrict__ esrc, const int* __restrict__ edst,
                               const float* __restrict__ ew, int e) {
    int i = blockIdx.x * blockDim.x + threadIdx.x;
    if (i < e) {
        int d = edst[i];
        int p = g_rowstart[d] + atomicAdd(&g_cnt[d], 1);
        g_csrs[p] = esrc[i];
        g_csrw[p] = ew[i];
    }
}

// ---------------- W^T split (fp16 hi/mid) + term0 convert ----------------
__global__ void wprep_kernel(const float* __restrict__ W) {  // W [1024,128]
    int i = blockIdx.x * blockDim.x + threadIdx.x;
    if (i < 1024 * 128) {
        int k = i >> 7, nn = i & 127;
        __half h, m;
        split_f16(W[i], h, m);
        g_wth[nn * 1024 + k] = h;
        g_wtm[nn * 1024 + k] = m;
    }
}
__global__ void conv0_kernel(const float* __restrict__ src, __half* __restrict__ dst, int n4) {
    int i = blockIdx.x * blockDim.x + threadIdx.x;
    if (i >= n4) return;
    float4 x = ((const float4*)src)[i];
    __half2 a = __floats2half2_rn(x.x, x.y);
    __half2 b = __floats2half2_rn(x.z, x.w);
    ((uint2*)dst)[i] = make_uint2(*(uint32_t*)&a, *(uint32_t*)&b);
}

// ---------------- SpMM: fp16 gather, fp32 accumulate, fp16 store ----------------
__global__ void spmm_kernel(const __half* __restrict__ X, __half* __restrict__ Y, int n) {
    int node = blockIdx.x * blockDim.y + threadIdx.y;
    if (node >= n) return;
    int lane = threadIdx.x;
    int p = g_rowstart[node], end = g_rowstart[node + 1];
    float4 acc = make_float4(0.f, 0.f, 0.f, 0.f);
    const uint2* Xv = (const uint2*)X;   // 4 halves per uint2
    for (; p + 4 <= end; p += 4) {
        int s0 = __ldg(&g_csrs[p]),     s1 = __ldg(&g_csrs[p + 1]);
        int s2 = __ldg(&g_csrs[p + 2]), s3 = __ldg(&g_csrs[p + 3]);
        float w0 = __ldg(&g_csrw[p]),     w1 = __ldg(&g_csrw[p + 1]);
        float w2 = __ldg(&g_csrw[p + 2]), w3 = __ldg(&g_csrw[p + 3]);
        uint2 x0 = __ldg(&Xv[s0 * 32 + lane]);
        uint2 x1 = __ldg(&Xv[s1 * 32 + lane]);
        uint2 x2 = __ldg(&Xv[s2 * 32 + lane]);
        uint2 x3 = __ldg(&Xv[s3 * 32 + lane]);
        float2 a, b;
        a = __half22float2(*(__half2*)&x0.x); b = __half22float2(*(__half2*)&x0.y);
        acc.x += w0 * a.x; acc.y += w0 * a.y; acc.z += w0 * b.x; acc.w += w0 * b.y;
        a = __half22float2(*(__half2*)&x1.x); b = __half22float2(*(__half2*)&x1.y);
        acc.x += w1 * a.x; acc.y += w1 * a.y; acc.z += w1 * b.x; acc.w += w1 * b.y;
        a = __half22float2(*(__half2*)&x2.x); b = __half22float2(*(__half2*)&x2.y);
        acc.x += w2 * a.x; acc.y += w2 * a.y; acc.z += w2 * b.x; acc.w += w2 * b.y;
        a = __half22float2(*(__half2*)&x3.x); b = __half22float2(*(__half2*)&x3.y);
        acc.x += w3 * a.x; acc.y += w3 * a.y; acc.z += w3 * b.x; acc.w += w3 * b.y;
    }
    for (; p < end; ++p) {
        int s = __ldg(&g_csrs[p]);
        float w = __ldg(&g_csrw[p]);
        uint2 x = __ldg(&Xv[s * 32 + lane]);
        float2 a = __half22float2(*(__half2*)&x.x), b = __half22float2(*(__half2*)&x.y);
        acc.x += w * a.x; acc.y += w * a.y; acc.z += w * b.x; acc.w += w * b.y;
    }
    __half2 h0 = __floats2half2_rn(acc.x, acc.y);
    __half2 h1 = __floats2half2_rn(acc.z, acc.w);
    ((uint2*)Y)[node * 32 + lane] = make_uint2(*(uint32_t*)&h0, *(uint32_t*)&h1);
}

// ---------------- GEMM: out[N,128] = cat_f16[N,1024] @ (Wh+Wm)[1024,128] + bias ----------
#define A_STRB 144
#define TILE_BYTES (128 * A_STRB)
#define SM_GEMM (3 * TILE_BYTES)

__global__ void __launch_bounds__(256, 2) krylov_gemm(
    const __half* __restrict__ terms,
    const __half* __restrict__ wth, const __half* __restrict__ wtm,
    const float* __restrict__ bias, float* __restrict__ out, int n)
{
    extern __shared__ char smem[];
    char* sA  = smem;
    char* sBh = smem + TILE_BYTES;
    char* sBm = smem + 2 * TILE_BYTES;
    const uint32_t uA = smem_u32(sA), uBh = smem_u32(sBh), uBm = smem_u32(sBm);

    const int tid = threadIdx.x, lane = tid & 31, wid = tid >> 5;
    const int warp_m = (wid & 3) * 32;
    const int warp_n = (wid >> 2) * 64;
    const int r0 = blockIdx.x * 128;

    const int a_rin = (lane & 7) + ((lane >> 3) & 1) * 8;
    const int a_k8  = (lane >> 4);
    const int b_nrow = (lane & 7) + (lane >> 4) * 8;
    const int b_k8   = (lane >> 3) & 1;
    const uint32_t aoff0 = (uint32_t)((warp_m + a_rin) * A_STRB + a_k8 * 16);
    const uint32_t aoff1 = aoff0 + 16 * A_STRB;
    const uint32_t boffb = (uint32_t)((warp_n + b_nrow) * A_STRB + b_k8 * 16);

    float acc[2][4][2][4];
    #pragma unroll
    for (int i = 0; i < 2; i++)
        #pragma unroll
        for (int j = 0; j < 4; j++)
            #pragma unroll
            for (int k = 0; k < 2; k++)
                #pragma unroll
                for (int l = 0; l < 4; l++) acc[i][j][k][l] = 0.f;

    for (int kc = 0; kc < 1024; kc += 64) {
        const int term = kc >> 7;
        const int col0 = kc & 127;
        const __half* A = terms + ((size_t)term * NPAD + r0) * 128 + col0;
        #pragma unroll
        for (int it = 0; it < 4; ++it) {
            int idx = tid + it * 256;
            int row = idx >> 3, q = idx & 7;
            uint32_t so = (uint32_t)(row * A_STRB + q * 16);
            *(uint4*)(sA + so) = __ldg((const uint4*)(A + (size_t)row * 128) + q);
        }
        #pragma unroll
        for (int it = 0; it < 4; ++it) {
            int idx = tid + it * 256;
            int nr = idx >> 3, q = idx & 7;
            uint32_t so = (uint32_t)(nr * A_STRB + q * 16);
            *(uint4*)(sBh + so) = __ldg((const uint4*)(wth + nr * 1024 + kc) + q);
            *(uint4*)(sBm + so) = __ldg((const uint4*)(wtm + nr * 1024 + kc) + q);
        }
        __syncthreads();
        #pragma unroll
        for (int ks = 0; ks < 4; ++ks) {
            const uint32_t kso = ks * 32;
            uint32_t a0[4], a1[4];
            ldsm4(a0, uA + aoff0 + kso);
            ldsm4(a1, uA + aoff1 + kso);
            #pragma unroll
            for (int np = 0; np < 4; ++np) {
                const uint32_t bo = boffb + np * 16 * A_STRB + kso;
                uint32_t bh[4], bm[4];
                ldsm4(bh, uBh + bo);
                mma16816(acc[0][np][0], a0, bh + 0);
                mma16816(acc[0][np][1], a0, bh + 2);
                mma16816(acc[1][np][0], a1, bh + 0);
                mma16816(acc[1][np][1], a1, bh + 2);
                ldsm4(bm, uBm + bo);
                mma16816(acc[0][np][0], a0, bm + 0);
                mma16816(acc[0][np][1], a0, bm + 2);
                mma16816(acc[1][np][0], a1, bm + 0);
                mma16816(acc[1][np][1], a1, bm + 2);
            }
        }
        __syncthreads();
    }

    const int g = lane >> 2, t4 = lane & 3;
    #pragma unroll
    for (int mb = 0; mb < 2; ++mb) {
        int r = r0 + warp_m + mb * 16 + g;
        #pragma unroll
        for (int np = 0; np < 4; ++np) {
            #pragma unroll
            for (int blk = 0; blk < 2; ++blk) {
                int col = warp_n + np * 16 + blk * 8 + 2 * t4;
                float b0 = __ldg(&bias[col]), b1 = __ldg(&bias[col + 1]);
                float* a = acc[mb][np][blk];
                if (r < n)
                    *(float2*)(out + (size_t)r * 128 + col) = make_float2(a[0] + b0, a[1] + b1);
                if (r + 8 < n)
                    *(float2*)(out + (size_t)(r + 8) * 128 + col) = make_float2(a[2] + b0, a[3] + b1);
            }
        }
    }
}

// ---------------- launch ----------------
extern "C" void kernel_launch(void* const* d_in, const int* in_sizes, int n_in,
                              void* d_out, int out_size) {
    const float* input = (const float*)d_in[0];
    const int*   esrc  = (const int*)d_in[1];
    const int*   edst  = (const int*)d_in[2];
    const float* ew    = (const float*)d_in[3];
    const float* W     = (const float*)d_in[4];
    const float* bias  = (const float*)d_in[5];
    float*       out   = (float*)d_out;

    int n = in_sizes[0] / F;
    int e = in_sizes[1];

    __half *terms = nullptr, *wth = nullptr, *wtm = nullptr;
    cudaGetSymbolAddress((void**)&terms, g_terms);
    cudaGetSymbolAddress((void**)&wth, g_wth);
    cudaGetSymbolAddress((void**)&wtm, g_wtm);

    static cudaStream_t s2 = nullptr;
    static cudaEvent_t ev0, ev1;
    if (!s2) {
        cudaFuncSetAttribute(krylov_gemm, cudaFuncAttributeMaxDynamicSharedMemorySize, SM_GEMM);
        cudaStreamCreateWithFlags(&s2, cudaStreamNonBlocking);
        cudaEventCreateWithFlags(&ev0, cudaEventDisableTiming);
        cudaEventCreateWithFlags(&ev1, cudaEventDisableTiming);
    }

    const int nb = (n + 1023) / 1024;

    // fork: CSR build (latency/atomic-bound) on s2, prep (bandwidth) on s0
    cudaEventRecord(ev0, 0);
    cudaStreamWaitEvent(s2, ev0, 0);
    zero_counts_kernel<<<(n + 255) / 256, 256, 0, s2>>>(n);
    hist_kernel<<<(e + 255) / 256, 256, 0, s2>>>(edst, e);
    scanA_kernel<<<nb, 1024, 0, s2>>>(n);
    scanB_kernel<<<1, 64, 0, s2>>>(nb);
    scanC_kernel<<<nb, 1024, 0, s2>>>(n);
    scatter_kernel<<<(e + 255) / 256, 256, 0, s2>>>(esrc, edst, ew, e);

    wprep_kernel<<<(1024 * 128 + 255) / 256, 256>>>(W);
    conv0_kernel<<<(n * 32 + 255) / 256, 256>>>(input, terms, n * 32);

    cudaEventRecord(ev1, s2);
    cudaStreamWaitEvent(0, ev1, 0);

    // Krylov chain entirely in fp16
    dim3 spmm_block(32, 8);
    int spmm_grid = (n + 7) / 8;
    for (int t = 1; t < NBLK; ++t)
        spmm_kernel<<<spmm_grid, spmm_block>>>(terms + (size_t)(t - 1) * NPAD * F,
                                               terms + (size_t)t * NPAD * F, n);

    // single tensor-core GEMM (fp16 x (Wh+Wm)) + bias
    krylov_gemm<<<(n + 127) / 128, 256, SM_GEMM>>>(terms, wth, wtm, bias, out, n);
}